// round 4
// baseline (speedup 1.0000x reference)
#include <cuda_runtime.h>
#include <cstdint>
#include <cstddef>

// Problem constants
// B=2, G=4, N=1024, H=16, dq=64, dv=64  -> BGH = 128
#define NSEQ   1024
#define DHEAD  64
#define NBGH   128
#define NQTILE 16     // 1024/64 q tiles

// Head-major scratch: [bgh][n][d], fp32
__device__ float g_Qh[(size_t)NBGH * NSEQ * DHEAD];
__device__ float g_Kh[(size_t)NBGH * NSEQ * DHEAD];
__device__ float g_Vh[(size_t)NBGH * NSEQ * DHEAD];

// ---------------------------------------------------------------------------
// Pre-pass: transpose (b,g,n, d*16+h) -> [bg*16+h][n][d]
// One block per (tensor row). 256 threads, each loads one float4 (1024 floats/row).
// ---------------------------------------------------------------------------
__global__ void transpose_heads_kernel(const float* __restrict__ q,
                                       const float* __restrict__ k,
                                       const float* __restrict__ v) {
    const int t = blockIdx.y;
    const float* src = (t == 0) ? q : (t == 1) ? k : v;
    float* dst = (t == 0) ? g_Qh : (t == 1) ? g_Kh : g_Vh;

    const size_t row = blockIdx.x;         // bg*1024 + n, 0..8191
    const float4* s4 = reinterpret_cast<const float4*>(src + row * 1024);

    __shared__ float sm[1024 + 32];        // padded: idx + (idx>>5)

    float4 val = s4[threadIdx.x];
    int e0 = threadIdx.x * 4;
    int p  = e0 + (e0 >> 5);               // all 4 elements share the same pad
    sm[p + 0] = val.x;
    sm[p + 1] = val.y;
    sm[p + 2] = val.z;
    sm[p + 3] = val.w;
    __syncthreads();

    const int bg = (int)(row >> 10);
    const int n  = (int)(row & 1023);

#pragma unroll
    for (int j = 0; j < 4; j++) {
        int e = threadIdx.x + j * 256;     // 0..1023
        int h = e >> 6;
        int d = e & 63;
        int idx = d * 16 + h;              // source channel index
        float x = sm[idx + (idx >> 5)];
        dst[((size_t)(bg * 16 + h) * NSEQ + n) * DHEAD + d] = x;
    }
}

// ---------------------------------------------------------------------------
// Flash attention main kernel.
// Grid: (16 q-tiles, 128 bgh). Block: 128 threads.
// Thread (tx = tid&7, ty = tid>>3) owns a 4(rows) x 8(cols) micro-tile.
// Smem (dynamic, 64KB): Qt, Kt (transposed + XOR-swizzled), Vs (row-major),
// Ps (transposed + swizzled probabilities).
// Swizzle: element [d][n] stored at d*64 + (n ^ (((d>>2)&15)<<2)).
// ---------------------------------------------------------------------------
__global__ __launch_bounds__(128)
void attn_kernel(const float* __restrict__ bias, float* __restrict__ out) {
    extern __shared__ float smem[];
    float* Qt = smem;            // 4096 floats
    float* Kt = smem + 4096;
    float* Vs = smem + 8192;
    float* Ps = smem + 12288;

    const int tid = threadIdx.x;
    const int tx = tid & 7;
    const int ty = tid >> 3;
    const int r0 = ty * 4;       // 0..60
    const int c0 = tx * 8;       // 0..56

    const int qtile = blockIdx.x;
    const int by    = blockIdx.y;          // bgh = bg*16 + h
    const int qbase = qtile * 64;
    const int g     = (by >> 4) & 3;

    const float* Qp    = g_Qh + ((size_t)by * NSEQ + qbase) * DHEAD;
    const float* biasg = bias + (size_t)g * NSEQ * NSEQ;

    // Load Q tile transposed+swizzled: Qt[d][n]
#pragma unroll
    for (int j = 0; j < 8; j++) {
        int f  = tid + j * 128;            // float4 index, 0..1023
        int n  = f >> 4;
        int d4 = f & 15;
        float4 val = *reinterpret_cast<const float4*>(Qp + n * 64 + d4 * 4);
        int base = (d4 * 4) * 64 + (n ^ (d4 << 2));
        Qt[base      ] = val.x;
        Qt[base +  64] = val.y;
        Qt[base + 128] = val.z;
        Qt[base + 192] = val.w;
    }

    float o[4][8];
    float m_i[4], l_i[4];
#pragma unroll
    for (int ri = 0; ri < 4; ri++) {
        m_i[ri] = -1e30f;
        l_i[ri] = 0.0f;
#pragma unroll
        for (int ci = 0; ci < 8; ci++) o[ri][ci] = 0.0f;
    }

    for (int kt = 0; kt < 16; kt++) {
        __syncthreads();   // previous iteration's PV reads are done

        const float* Kp = g_Kh + ((size_t)by * NSEQ + kt * 64) * DHEAD;
        const float* Vp = g_Vh + ((size_t)by * NSEQ + kt * 64) * DHEAD;

        // K tile transposed+swizzled: Kt[d][m]
#pragma unroll
        for (int j = 0; j < 8; j++) {
            int f  = tid + j * 128;
            int n  = f >> 4;
            int d4 = f & 15;
            float4 val = *reinterpret_cast<const float4*>(Kp + n * 64 + d4 * 4);
            int base = (d4 * 4) * 64 + (n ^ (d4 << 2));
            Kt[base      ] = val.x;
            Kt[base +  64] = val.y;
            Kt[base + 128] = val.z;
            Kt[base + 192] = val.w;
        }
        // V tile row-major copy: Vs[m][c]
#pragma unroll
        for (int j = 0; j < 8; j++) {
            int f = tid + j * 128;
            reinterpret_cast<float4*>(Vs)[f] =
                reinterpret_cast<const float4*>(Vp)[f];
        }
        __syncthreads();

        // ---- S = Q * K^T (64x64x64), 4x8 micro-tile ----
        float s[4][8];
#pragma unroll
        for (int ri = 0; ri < 4; ri++)
#pragma unroll
            for (int ci = 0; ci < 8; ci++) s[ri][ci] = 0.0f;

#pragma unroll 4
        for (int k = 0; k < 64; k++) {
            int swz = (k >> 2) << 2;
            float4 a  = *reinterpret_cast<const float4*>(&Qt[k * 64 + (r0 ^ swz)]);
            float4 b0 = *reinterpret_cast<const float4*>(&Kt[k * 64 + (c0 ^ swz)]);
            float4 b1 = *reinterpret_cast<const float4*>(&Kt[k * 64 + ((c0 ^ swz) ^ 4)]);
            float av[4] = {a.x, a.y, a.z, a.w};
            float bv[8] = {b0.x, b0.y, b0.z, b0.w, b1.x, b1.y, b1.z, b1.w};
#pragma unroll
            for (int ri = 0; ri < 4; ri++)
#pragma unroll
                for (int ci = 0; ci < 8; ci++)
                    s[ri][ci] += av[ri] * bv[ci];
        }

        // ---- scale, bias, online softmax ----
#pragma unroll
        for (int ri = 0; ri < 4; ri++) {
            const float* bp = biasg + (size_t)(qbase + r0 + ri) * NSEQ + kt * 64 + c0;
            float4 bb0 = *reinterpret_cast<const float4*>(bp);
            float4 bb1 = *reinterpret_cast<const float4*>(bp + 4);
            s[ri][0] = s[ri][0] * 0.125f - bb0.x;
            s[ri][1] = s[ri][1] * 0.125f - bb0.y;
            s[ri][2] = s[ri][2] * 0.125f - bb0.z;
            s[ri][3] = s[ri][3] * 0.125f - bb0.w;
            s[ri][4] = s[ri][4] * 0.125f - bb1.x;
            s[ri][5] = s[ri][5] * 0.125f - bb1.y;
            s[ri][6] = s[ri][6] * 0.125f - bb1.z;
            s[ri][7] = s[ri][7] * 0.125f - bb1.w;

            float mx = s[ri][0];
#pragma unroll
            for (int ci = 1; ci < 8; ci++) mx = fmaxf(mx, s[ri][ci]);
            // row reduce across the 8-lane tx group (lane bits 0..2)
            mx = fmaxf(mx, __shfl_xor_sync(0xffffffffu, mx, 1));
            mx = fmaxf(mx, __shfl_xor_sync(0xffffffffu, mx, 2));
            mx = fmaxf(mx, __shfl_xor_sync(0xffffffffu, mx, 4));

            float mnew = fmaxf(m_i[ri], mx);
            float corr = __expf(m_i[ri] - mnew);
            float sum = 0.0f;
#pragma unroll
            for (int ci = 0; ci < 8; ci++) {
                float pv = __expf(s[ri][ci] - mnew);
                s[ri][ci] = pv;
                sum += pv;
            }
            sum += __shfl_xor_sync(0xffffffffu, sum, 1);
            sum += __shfl_xor_sync(0xffffffffu, sum, 2);
            sum += __shfl_xor_sync(0xffffffffu, sum, 4);

            l_i[ri] = l_i[ri] * corr + sum;
            m_i[ri] = mnew;
#pragma unroll
            for (int ci = 0; ci < 8; ci++) o[ri][ci] *= corr;
        }

        // ---- write P transposed+swizzled: Ps[m][r] ----
#pragma unroll
        for (int ci = 0; ci < 8; ci++) {
            int c = c0 + ci;                  // m index
            int swz = (c >> 2) << 2;
            float4 val = make_float4(s[0][ci], s[1][ci], s[2][ci], s[3][ci]);
            *reinterpret_cast<float4*>(&Ps[c * 64 + (r0 ^ swz)]) = val;
        }
        __syncthreads();

        // ---- O += P * V (64x64x64) ----
#pragma unroll 4
        for (int m = 0; m < 64; m++) {
            int swz = (m >> 2) << 2;
            float4 a  = *reinterpret_cast<const float4*>(&Ps[m * 64 + (r0 ^ swz)]);
            float4 v0 = *reinterpret_cast<const float4*>(&Vs[m * 64 + c0]);
            float4 v1 = *reinterpret_cast<const float4*>(&Vs[m * 64 + c0 + 4]);
            float av[4] = {a.x, a.y, a.z, a.w};
            float vv[8] = {v0.x, v0.y, v0.z, v0.w, v1.x, v1.y, v1.z, v1.w};
#pragma unroll
            for (int ri = 0; ri < 4; ri++)
#pragma unroll
                for (int ci = 0; ci < 8; ci++)
                    o[ri][ci] += av[ri] * vv[ci];
        }
    }

    // ---- epilogue: normalize and write out [bgh][n][dv] ----
#pragma unroll
    for (int ri = 0; ri < 4; ri++) {
        float inv = 1.0f / l_i[ri];
        float* op = out + ((size_t)by * NSEQ + qbase + r0 + ri) * DHEAD + c0;
        float4 w0 = make_float4(o[ri][0] * inv, o[ri][1] * inv,
                                o[ri][2] * inv, o[ri][3] * inv);
        float4 w1 = make_float4(o[ri][4] * inv, o[ri][5] * inv,
                                o[ri][6] * inv, o[ri][7] * inv);
        *reinterpret_cast<float4*>(op)     = w0;
        *reinterpret_cast<float4*>(op + 4) = w1;
    }
}

// ---------------------------------------------------------------------------
extern "C" void kernel_launch(void* const* d_in, const int* in_sizes, int n_in,
                              void* d_out, int out_size) {
    (void)in_sizes; (void)n_in; (void)out_size;
    const float* q    = reinterpret_cast<const float*>(d_in[0]);
    const float* k    = reinterpret_cast<const float*>(d_in[1]);
    const float* v    = reinterpret_cast<const float*>(d_in[2]);
    const float* bias = reinterpret_cast<const float*>(d_in[3]);
    float* out = reinterpret_cast<float*>(d_out);

    const int smem_bytes = 4 * 4096 * sizeof(float);  // 64 KB
    cudaFuncSetAttribute(attn_kernel,
                         cudaFuncAttributeMaxDynamicSharedMemorySize, smem_bytes);

    dim3 tgrid(8 * 1024, 3);     // B*G*N rows, {Q,K,V}
    transpose_heads_kernel<<<tgrid, 256>>>(q, k, v);

    dim3 agrid(NQTILE, NBGH);
    attn_kernel<<<agrid, 128, smem_bytes>>>(bias, out);
}